// round 8
// baseline (speedup 1.0000x reference)
#include <cuda_runtime.h>

// S4D SSM layer, recurrence formulation of the FFT causal conv.
// Shapes hardcoded: L=4096, B=4, D=1024, N=16.
//
// pass1: complex local scan per chunk, software-pipelined x loads (ping-pong)
// pass2: carry propagation across chunks, all 32 chunk states in regs
// pass3: 2nd-order REAL recurrence u_i = a u_{i-1} + b u_{i-2} + pr x_i - g x_{i-1},
//        software-pipelined loads.

#define NSTATE 16
#define PACKS  8
#define TCHUNK 128
#define LOG2_TCHUNK 7
#define NCH    32              // L / TCHUNK
#define D_DIM  1024
#define B_SZ   4
#define XS     (B_SZ * D_DIM)  // float stride per timestep = 4096
#define SCALE_F 0.25f

typedef unsigned long long ull;

__device__ __forceinline__ ull pack2(float lo, float hi) {
    ull r; asm("mov.b64 %0, {%1,%2};" : "=l"(r) : "f"(lo), "f"(hi)); return r;
}
__device__ __forceinline__ void unpack2(ull v, float& a, float& b) {
    asm("mov.b64 {%0,%1}, %2;" : "=f"(a), "=f"(b) : "l"(v));
}
__device__ __forceinline__ ull fma2(ull a, ull b, ull c) {
    ull d; asm("fma.rn.f32x2 %0, %1, %2, %3;" : "=l"(d) : "l"(a), "l"(b), "l"(c)); return d;
}
__device__ __forceinline__ ull mul2(ull a, ull b) {
    ull d; asm("mul.rn.f32x2 %0, %1, %2;" : "=l"(d) : "l"(a), "l"(b)); return d;
}
__device__ __forceinline__ ull add2(ull a, ull b) {
    ull d; asm("add.rn.f32x2 %0, %1, %2;" : "=l"(d) : "l"(a), "l"(b)); return d;
}
__device__ __forceinline__ ull neg2(ull a) {       // negate both packed floats (alu pipe)
    return a ^ 0x8000000080000000ULL;
}

// chunk-boundary states: ((c*B + b)*NSTATE + n)*D + d  — coalesced in d
__device__ float2 g_state[1 << 21];   // 16 MB static scratch

__device__ __forceinline__ void q_of(float dt, float lar, float aim,
                                     float& qr, float& qi)
{
    float zr = -0.5f * dt * __expf(lar);
    float zi =  0.5f * dt * aim;
    float omz = 1.0f - zr;
    float inv = __fdividef(1.0f, omz * omz + zi * zi);
    qr = (1.0f - zr * zr - zi * zi) * inv;
    qi = 2.0f * zi * inv;
}

__device__ __forceinline__ float silu_of(float z) {
    float sg = __fdividef(1.0f, 1.0f + __expf(-z));
    return z * sg;
}

// ---------------------------------------------------------------------------
// pass1: complex local scan, 1 thread per d, ping-pong pipelined loads.
// ---------------------------------------------------------------------------
__device__ __forceinline__ void c8(const ull* Qr, const ull* Qi,
                                   ull* Sr, ull* Sm, const float* xv)
{
#pragma unroll
    for (int u = 0; u < 8; u++) {
        ull X2 = pack2(xv[u], xv[u]);
#pragma unroll
        for (int j = 0; j < PACKS; j++) {
            // sr' = qr*sr + qi*m + x   (m = -si)
            ull t   = fma2(Qi[j], Sm[j], X2);
            ull nsr = fma2(Qr[j], Sr[j], t);
            // m'  = qr*m - qi*sr
            ull nm  = fma2(Qr[j], Sm[j], neg2(mul2(Qi[j], Sr[j])));
            Sr[j] = nsr; Sm[j] = nm;
        }
    }
}

__global__ void __launch_bounds__(128) s4d_pass1(
    const float* __restrict__ x, const float* __restrict__ log_dt,
    const float* __restrict__ log_A_real, const float* __restrict__ A_imag)
{
    int d = blockIdx.x * 128 + threadIdx.x;
    int b = blockIdx.y;
    int c = blockIdx.z;

    float dt = __expf(log_dt[d]);

    ull Qr[PACKS], Qi[PACKS], Sr[PACKS], Sm[PACKS];
#pragma unroll
    for (int j = 0; j < PACKS; j++) {
        float qr0, qi0, qr1, qi1;
        q_of(dt, log_A_real[d*NSTATE + 2*j],   A_imag[d*NSTATE + 2*j],   qr0, qi0);
        q_of(dt, log_A_real[d*NSTATE + 2*j+1], A_imag[d*NSTATE + 2*j+1], qr1, qi1);
        Qr[j] = pack2(qr0, qr1);
        Qi[j] = pack2(qi0, qi1);
        Sr[j] = 0ull; Sm[j] = 0ull;   // Sm holds m = -si
    }

    const float* xq = x + ((long long)(c * TCHUNK) * B_SZ + b) * D_DIM + d;

    float va[8], vb[8];
#pragma unroll
    for (int u = 0; u < 8; u++) va[u] = xq[(long long)u * XS];
    xq += 8 * XS;

    // groups g0..g15; pipeline: load next, compute current
    for (int k = 0; k < 7; k++) {
#pragma unroll
        for (int u = 0; u < 8; u++) vb[u] = xq[(long long)u * XS];
        xq += 8 * XS;
        c8(Qr, Qi, Sr, Sm, va);
#pragma unroll
        for (int u = 0; u < 8; u++) va[u] = xq[(long long)u * XS];
        xq += 8 * XS;
        c8(Qr, Qi, Sr, Sm, vb);
    }
#pragma unroll
    for (int u = 0; u < 8; u++) vb[u] = xq[(long long)u * XS];
    c8(Qr, Qi, Sr, Sm, va);   // g14
    c8(Qr, Qi, Sr, Sm, vb);   // g15

    float2* st = g_state + (((long long)c * B_SZ + b) * NSTATE) * D_DIM + d;
#pragma unroll
    for (int j = 0; j < PACKS; j++) {
        float r0, r1, m0, m1;
        unpack2(Sr[j], r0, r1); unpack2(Sm[j], m0, m1);
        st[(long long)(2*j    ) * D_DIM] = make_float2(r0, -m0);
        st[(long long)(2*j + 1) * D_DIM] = make_float2(r1, -m1);
    }
}

// ---------------------------------------------------------------------------
// pass2: preload all 32 chunk states (MLP=32), scan in regs, store back.
// ---------------------------------------------------------------------------
__global__ void __launch_bounds__(256) s4d_pass2(
    const float* __restrict__ log_dt, const float* __restrict__ log_A_real,
    const float* __restrict__ A_imag)
{
    int id = blockIdx.x * 256 + threadIdx.x;
    int d = id % D_DIM;
    int n = (id / D_DIM) % NSTATE;
    int b = id / (D_DIM * NSTATE);

    float dt = __expf(log_dt[d]);
    float qr, qi;
    q_of(dt, log_A_real[d * NSTATE + n], A_imag[d * NSTATE + n], qr, qi);

#pragma unroll
    for (int i = 0; i < LOG2_TCHUNK; i++) {
        float nr = qr * qr - qi * qi;
        float ni = 2.0f * qr * qi;
        qr = nr; qi = ni;
    }

    long long base    = ((long long)b * NSTATE + n) * D_DIM + d;
    const long long cstride = (long long)B_SZ * NSTATE * D_DIM;

    float2 t[NCH];
#pragma unroll
    for (int c = 0; c < NCH; c++)
        t[c] = g_state[base + (long long)c * cstride];

    float2 s = t[0];
#pragma unroll
    for (int c = 1; c < NCH; c++) {
        float nr = fmaf(qr, s.x, fmaf(-qi, s.y, t[c].x));
        float ni = fmaf(qr, s.y, fmaf( qi, s.x, t[c].y));
        s.x = nr; s.y = ni;
        t[c] = s;
    }

#pragma unroll
    for (int c = 1; c < NCH; c++)
        g_state[base + (long long)c * cstride] = t[c];
}

// ---------------------------------------------------------------------------
// pass3: 2nd-order real recurrence on u = Re(p*s) + residual + silu,
// ping-pong pipelined loads.
// ---------------------------------------------------------------------------
__device__ __forceinline__ float rstep(const ull* A, const ull* Bc,
                                       const ull* Pr, const ull* nG,
                                       const ull* V, ull* VD,
                                       float xc, float xm)
{
    ull Xc = pack2(xc, xc);
    ull Xm = pack2(xm, xm);
    ull acc0 = 0ull, acc1 = 0ull;
#pragma unroll
    for (int j = 0; j < PACKS; j++) {
        ull w  = fma2(Pr[j], Xc, mul2(nG[j], Xm));
        ull t  = fma2(Bc[j], VD[j], w);
        ull nv = fma2(A[j], V[j], t);
        VD[j] = nv;
        if (j & 1) acc1 = add2(acc1, nv);
        else       acc0 = add2(acc0, nv);
    }
    ull s = add2(acc0, acc1);
    float lo, hi; unpack2(s, lo, hi);
    return lo + hi;
}

// one group of 8 steps; parity of U0/U1 role-swap preserved (even count)
__device__ __forceinline__ void r8(const ull* A, const ull* Bc,
                                   const ull* Pr, const ull* nG,
                                   ull* U0, ull* U1,
                                   const float* xv, float& xm,
                                   float dpar, float* oq)
{
#pragma unroll
    for (int u = 0; u < 8; u++) {
        float prev = (u == 0) ? xm : xv[u - 1];
        float y = (u & 1) ? rstep(A, Bc, Pr, nG, U0, U1, xv[u], prev)
                          : rstep(A, Bc, Pr, nG, U1, U0, xv[u], prev);
        oq[(long long)u * XS] = silu_of(fmaf(xv[u], dpar, y));
    }
    xm = xv[7];
}

__global__ void __launch_bounds__(128) s4d_pass3(
    const float* __restrict__ x, const float* __restrict__ log_dt,
    const float* __restrict__ log_A_real, const float* __restrict__ A_imag,
    const float* __restrict__ Bparam, const float* __restrict__ Cparam,
    const float* __restrict__ Dparam, float* __restrict__ out)
{
    int d = blockIdx.x * 128 + threadIdx.x;
    int b = blockIdx.y;
    int c = blockIdx.z;

    float dt = __expf(log_dt[d]);
    const float* xp = x + ((long long)(c * TCHUNK) * B_SZ + b) * D_DIM + d;
    float* op = out + ((long long)(c * TCHUNK) * B_SZ + b) * D_DIM + d;
    float dpar = Dparam[d];

    float xs0 = xp[0];

    ull A[PACKS], Bc[PACKS], Pr[PACKS], nG[PACKS], U0[PACKS], U1[PACKS];
    float y0 = 0.0f;

#pragma unroll
    for (int j = 0; j < PACKS; j++) {
        float aa[2], bb[2], prr[2], gg[2], u0[2], um1[2];
#pragma unroll
        for (int k = 0; k < 2; k++) {
            int n = d * NSTATE + 2 * j + k;
            float zr = -0.5f * dt * __expf(log_A_real[n]);
            float zi =  0.5f * dt * A_imag[n];
            float omz = 1.0f - zr;
            float inv = __fdividef(1.0f, omz * omz + zi * zi);
            float qr = (1.0f - zr * zr - zi * zi) * inv;
            float qi = 2.0f * zi * inv;
            float Br = Bparam[n * 2 + 0];
            float Bi = Bparam[n * 2 + 1];
            float Cr = Cparam[n * 2 + 0];
            float Ci = Cparam[n * 2 + 1];
            float ccr = Br * Cr - Bi * Ci;
            float cci = Br * Ci + Bi * Cr;
            float w = dt * SCALE_F * inv;
            float pr = w * (ccr * omz - cci * zi);
            float pi = w * (ccr * zi + cci * omz);

            aa[k]  = 2.0f * qr;
            bb[k]  = -(qr * qr + qi * qi);
            prr[k] = pr;
            gg[k]  = -(pr * qr + pi * qi);

            float sr = 0.0f, si = 0.0f;
            if (c > 0) {
                float2 v = g_state[(((long long)(c-1) * B_SZ + b) * NSTATE + 2*j + k) * D_DIM + d];
                sr = v.x; si = v.y;
            }
            um1[k] = pr * sr - pi * si;                    // u_{-1} = Re(p s)
            float pqr = pr * qr - pi * qi;
            float pqi = pr * qi + pi * qr;
            u0[k]  = pqr * sr - pqi * si + pr * xs0;       // u_0
            y0 += u0[k];
        }
        A[j]  = pack2(aa[0], aa[1]);
        Bc[j] = pack2(bb[0], bb[1]);
        Pr[j] = pack2(prr[0], prr[1]);
        nG[j] = pack2(gg[0], gg[1]);
        U0[j] = pack2(u0[0], u0[1]);    // u_0 (newest)
        U1[j] = pack2(um1[0], um1[1]);  // u_{-1}
    }

    op[0] = silu_of(fmaf(xs0, dpar, y0));

    // step i = 1: V = U0 (u_0), VD = U1 (u_{-1}) -> U1 := u_1 (newest)
    float xm = xs0;
    {
        float xc = xp[XS];
        float y = rstep(A, Bc, Pr, nG, U0, U1, xc, xm);
        op[XS] = silu_of(fmaf(xc, dpar, y));
        xm = xc;
    }

    // steps i = 2..121: 15 groups of 8, ping-pong pipelined
    const float* xq = xp + 2 * XS;
    float* oq = op + 2 * XS;

    float va[8], vb[8];
#pragma unroll
    for (int u = 0; u < 8; u++) va[u] = xq[(long long)u * XS];
    xq += 8 * XS;

    for (int k = 0; k < 7; k++) {
#pragma unroll
        for (int u = 0; u < 8; u++) vb[u] = xq[(long long)u * XS];
        xq += 8 * XS;
        r8(A, Bc, Pr, nG, U0, U1, va, xm, dpar, oq);
        oq += 8 * XS;
#pragma unroll
        for (int u = 0; u < 8; u++) va[u] = xq[(long long)u * XS];
        xq += 8 * XS;
        r8(A, Bc, Pr, nG, U0, U1, vb, xm, dpar, oq);
        oq += 8 * XS;
    }
    // g14 in va; load the 6-step tail, then compute g14 and tail
    float vt[6];
#pragma unroll
    for (int u = 0; u < 6; u++) vt[u] = xq[(long long)u * XS];

    r8(A, Bc, Pr, nG, U0, U1, va, xm, dpar, oq);
    oq += 8 * XS;

#pragma unroll
    for (int u = 0; u < 6; u++) {
        float prev = (u == 0) ? xm : vt[u - 1];
        float y = (u & 1) ? rstep(A, Bc, Pr, nG, U0, U1, vt[u], prev)
                          : rstep(A, Bc, Pr, nG, U1, U0, vt[u], prev);
        oq[(long long)u * XS] = silu_of(fmaf(vt[u], dpar, y));
    }
}

extern "C" void kernel_launch(void* const* d_in, const int* in_sizes, int n_in,
                              void* d_out, int out_size)
{
    const float* x      = (const float*)d_in[0];
    const float* log_dt = (const float*)d_in[1];
    const float* lar    = (const float*)d_in[2];
    const float* aim    = (const float*)d_in[3];
    const float* Bp     = (const float*)d_in[4];
    const float* Cp     = (const float*)d_in[5];
    const float* Dp     = (const float*)d_in[6];
    float* out = (float*)d_out;

    dim3 blk(128);
    dim3 grd(D_DIM / 128, B_SZ, NCH);   // (8, 4, 32) = 1024 blocks

    s4d_pass1<<<grd, blk>>>(x, log_dt, lar, aim);

    int total2 = B_SZ * NSTATE * D_DIM;      // 65536
    s4d_pass2<<<total2 / 256, 256>>>(log_dt, lar, aim);

    s4d_pass3<<<grd, blk>>>(x, log_dt, lar, aim, Bp, Cp, Dp, out);
}